// round 13
// baseline (speedup 1.0000x reference)
#include <cuda_runtime.h>
#include <cuda_bf16.h>
#include <math.h>

// Fixed shapes: cls_conv_out (4, 1029, 100, 100) fp32; rois (2000,4) int32.
// Only batch 3 used. Output (2000, 21, 1, 1) fp32.
#define KK       7
#define C1       21
#define NJL      49
#define H        100
#define W        100
#define HP       101
#define ROW_S    2124                 // HP*C1=2121 padded to mult of 4 (16B rows)
#define ROW4     (ROW_S / 4)          // 531
#define PLANE_S  (HP * ROW_S)
#define IN_BASE  (3 * 1029 * 10000)   // batch 3 offset
#define NS       10                   // y strips
#define RPS      10                   // rows per strip
#define SMEM_BYTES (RPS * ROW_S * 4)  // 84,960 B row buffers

// GLOBAL integral image (fully corrected), transposed c-innermost.
__device__ float g_integral[(size_t)NJL * PLANE_S];
// Look-back flags: g_flag[jl*NS + s] = strip s of plane jl fully stored.
__device__ unsigned g_flag[NJL * NS];

// ---------------------------------------------------------------------------
// Fused build: block=(strip s, jl); 21 warps = one channel each.
// Phase 1: stream 10 rows (load -> shuffle x-scan -> local y-acc -> STS into
//          per-row smem buffers in final transposed layout). No cross-strip dep.
// Phase 2: look-back: wait for strip s-1's flag, read its last row (= offset),
//          add to buffered rows; store LAST row first, release flag, store rest.
// ---------------------------------------------------------------------------
__global__ void __launch_bounds__(672, 2) fused_scan(const float* __restrict__ in) {
    const int s    = blockIdx.x;       // 0..9
    const int jl   = blockIdx.y;       // 0..48
    const int t    = threadIdx.x;
    const int c    = t >> 5;           // warp id == channel 0..20
    const int lane = t & 31;

    extern __shared__ __align__(16) float smt[];   // [RPS][ROW_S]

    // zero x=0 column (21) + tail padding (3) of every row buffer
    if (t < 24) {
        const int idx = (t < C1) ? t : (2121 + t - C1);
        #pragma unroll
        for (int r = 0; r < RPS; r++) smt[r * ROW_S + idx] = 0.0f;
    }

    const float4* src4 = (const float4*)(in + IN_BASE
                        + (size_t)jl * (C1 * H * W) + (size_t)c * (H * W));
    float* gplane = g_integral + (size_t)jl * PLANE_S;

    // ---- Phase 1: strip-local integral into smem row buffers
    float4 acc  = make_float4(0.f, 0.f, 0.f, 0.f);
    float4 vcur = make_float4(0.f, 0.f, 0.f, 0.f);
    if (lane < 25) vcur = src4[(s * RPS) * (W / 4) + lane];

    #pragma unroll
    for (int r = 0; r < RPS; r++) {
        float4 vnext = make_float4(0.f, 0.f, 0.f, 0.f);
        if (r < RPS - 1 && lane < 25)
            vnext = src4[(s * RPS + r + 1) * (W / 4) + lane];

        float s0 = vcur.x;
        float s1 = s0 + vcur.y;
        float s2 = s1 + vcur.z;
        float s3 = s2 + vcur.w;
        float run = s3;
        #pragma unroll
        for (int d = 1; d < 32; d <<= 1) {
            float u = __shfl_up_sync(0xffffffffu, run, d);
            if (lane >= d) run += u;
        }
        const float off = run - s3;
        acc.x += off + s0;
        acc.y += off + s1;
        acc.z += off + s2;
        acc.w += off + s3;

        // conflict-free scatter: bank stride 21*lane mod 32, 21 coprime 32
        if (lane < 25) {
            float* sl = smt + r * ROW_S + 84 * lane + C1 + c;
            sl[0]      = acc.x;
            sl[C1]     = acc.y;
            sl[2 * C1] = acc.z;
            sl[3 * C1] = acc.w;
        }
        vcur = vnext;
    }
    __syncthreads();

    // ---- Phase 2: look-back, correct, store
    float4 offs = make_float4(0.f, 0.f, 0.f, 0.f);
    if (s > 0) {
        if (t == 0) {
            const unsigned* fp = &g_flag[jl * NS + (s - 1)];
            unsigned v;
            do {
                asm volatile("ld.acquire.gpu.b32 %0, [%1];"
                             : "=r"(v) : "l"(fp) : "memory");
            } while (v == 0);
        }
        __syncthreads();   // leader-acquire + barrier: row below is visible
        if (t < ROW4)
            offs = ((const float4*)(gplane + (size_t)(s * RPS) * ROW_S))[t];
    } else {
        // strip 0 also writes the y=0 zero row
        if (t < ROW4)
            ((float4*)gplane)[t] = make_float4(0.f, 0.f, 0.f, 0.f);
    }

    // store LAST row first (it is strip s+1's offset), then publish flag
    if (t < ROW4) {
        float4 v = ((const float4*)(smt + (RPS - 1) * ROW_S))[t];
        v.x += offs.x; v.y += offs.y; v.z += offs.z; v.w += offs.w;
        ((float4*)(gplane + (size_t)(s * RPS + RPS) * ROW_S))[t] = v;
    }
    __syncthreads();
    if (t == 0) {
        const unsigned* fp = &g_flag[jl * NS + s];
        asm volatile("st.release.gpu.b32 [%0], %1;"
                     :: "l"(fp), "r"(1u) : "memory");
    }

    // remaining rows 1..9 of the strip
    if (t < ROW4) {
        #pragma unroll
        for (int r = 0; r < RPS - 1; r++) {
            float4 v = ((const float4*)(smt + r * ROW_S))[t];
            v.x += offs.x; v.y += offs.y; v.z += offs.z; v.w += offs.w;
            ((float4*)(gplane + (size_t)(s * RPS + r + 1) * ROW_S))[t] = v;
        }
    }
}

// ---------------------------------------------------------------------------
// Kernel C: one block per ROI. 336 active threads (16 jl-groups x 21 c);
// register pre-reduction, 21-thread final sum, warp softmax.
// Block 0 also clears the look-back flags for the next graph replay.
// ---------------------------------------------------------------------------
__global__ void pool_softmax(const int* __restrict__ rois,
                             float* __restrict__ out) {
    const int roi = blockIdx.x;
    const int t   = threadIdx.x;
    __shared__ float s_part[336];
    __shared__ float s_avg[C1];

    if (roi == 0) {
        for (int i = t; i < NJL * NS; i += blockDim.x) g_flag[i] = 0;
    }

    const int4 r = ((const int4*)rois)[roi];   // ymin, xmin, ymax, xmax
    const int ys = (r.z - r.x) / KK;
    const int xs = (r.w - r.y) / KK;

    if (t < 336) {
        const int c   = t % C1;
        const int jl0 = t / C1;   // 0..15
        float part = 0.0f;
        #pragma unroll
        for (int jl = jl0; jl < NJL; jl += 16) {
            const int j = jl / KK, l = jl - j * KK;
            const int y0 = r.x + j * ys, y1 = y0 + ys;
            const int x0 = r.y + l * xs, x1 = x0 + xs;
            const float* P = g_integral + (size_t)jl * PLANE_S;
            const float a = P[(size_t)y1 * ROW_S + x1 * C1 + c];
            const float b = P[(size_t)y0 * ROW_S + x1 * C1 + c];
            const float d = P[(size_t)y1 * ROW_S + x0 * C1 + c];
            const float e = P[(size_t)y0 * ROW_S + x0 * C1 + c];
            part += (a - b) - (d - e);
        }
        s_part[t] = part;
    }
    __syncthreads();

    if (t < C1) {
        float acc = 0.0f;
        #pragma unroll
        for (int g = 0; g < 16; g++) acc += s_part[g * C1 + t];
        s_avg[t] = acc / (49.0f * (float)(ys * xs));
    }
    __syncthreads();

    if (t < 32) {
        const bool act = t < C1;
        float v = act ? s_avg[t] : -INFINITY;
        float m = v;
        #pragma unroll
        for (int o = 16; o; o >>= 1) m = fmaxf(m, __shfl_xor_sync(0xffffffffu, m, o));
        float e = act ? expf(v - m) : 0.0f;
        float sum = e;
        #pragma unroll
        for (int o = 16; o; o >>= 1) sum += __shfl_xor_sync(0xffffffffu, sum, o);
        if (act) out[(size_t)roi * C1 + t] = e / sum;
    }
}

// ---------------------------------------------------------------------------
extern "C" void kernel_launch(void* const* d_in, const int* in_sizes, int n_in,
                              void* d_out, int out_size) {
    const float* x    = (const float*)d_in[0];
    const int*   rois = (const int*)d_in[1];
    float*       out  = (float*)d_out;
    const int n_rois  = in_sizes[1] / 4;   // 2000

    static int attr_done = 0;
    if (!attr_done) {
        cudaFuncSetAttribute(fused_scan,
                             cudaFuncAttributeMaxDynamicSharedMemorySize,
                             SMEM_BYTES);
        attr_done = 1;
    }

    dim3 gF(NS, NJL);                      // 10 x 49 = 490 blocks, 672 thr
    fused_scan<<<gF, 672, SMEM_BYTES>>>(x);

    pool_softmax<<<n_rois, 352>>>(rois, out);
}

// round 14
// speedup vs baseline: 1.4578x; 1.4578x over previous
#include <cuda_runtime.h>
#include <cuda_bf16.h>
#include <math.h>

// Fixed shapes: cls_conv_out (4, 1029, 100, 100) fp32; rois (2000,4) int32.
// Only batch 3 used. Output (2000, 21, 1, 1) fp32.
#define KK       7
#define C1       21
#define NJL      49
#define H        100
#define W        100
#define HP       101
#define ROW_S    2124                 // HP*C1=2121 padded to mult of 4 (16B rows)
#define PLANE_S  (HP * ROW_S)
#define IN_BASE  (3 * 1029 * 10000)   // batch 3 offset
#define RPB      4                    // y-rows per block in kernel A

// Integral image, transposed c-innermost: I[jl][y][x][c]; ~42 MB scratch.
__device__ float g_integral[(size_t)NJL * PLANE_S];

// ---------------------------------------------------------------------------
// Kernel A: block = (jl, 4 y-rows), 21 warps = one channel each.
// Each warp: 4 __ldcs float4 loads (evict-first: input is read once, keep L2
// for the integral), ONE 25-lane shuffle scan per row, conflict-free STS into
// the final transposed layout, 4 cp.async.bulk row stores, single wait.
// ---------------------------------------------------------------------------
__global__ void __launch_bounds__(672) build_xsum(const float* __restrict__ in) {
    const int ybase = RPB * blockIdx.x + 1;  // 1, 5, ..., 97
    const int jl    = blockIdx.y;            // 0..48
    const int t     = threadIdx.x;
    const int c     = t >> 5;                // warp id == channel 0..20
    const int lane  = t & 31;

    __shared__ __align__(16) float smt[RPB][ROW_S];  // final rows: smt[r][x*21+c]

    // zero x=0 column (21 floats) and tail padding (3 floats) of each row buf
    if (t < 24) {
        const int idx = (t < C1) ? t : (2121 + t - C1);
        #pragma unroll
        for (int r = 0; r < RPB; r++) smt[r][idx] = 0.0f;
    }

    // --- loads: lane l holds float4 covering x = 4l..4l+3 of each row
    const float4* src4 = (const float4*)(in + IN_BASE
                        + (size_t)jl * (C1 * H * W) + (size_t)c * (H * W));
    float4 v[RPB];
    if (lane < 25) {
        #pragma unroll
        for (int r = 0; r < RPB; r++)
            v[r] = __ldcs(&src4[(ybase - 1 + r) * (W / 4) + lane]);
    }

    // --- per-row: in-thread scan of 4 + one shfl_up scan over lanes,
    // scatter-store into transposed layout (out position x+1).
    // STS banks: 21*lane mod 32, 21 coprime 32 -> conflict-free.
    #pragma unroll
    for (int r = 0; r < RPB; r++) {
        float s0 = v[r].x;
        float s1 = s0 + v[r].y;
        float s2 = s1 + v[r].z;
        float s3 = s2 + v[r].w;
        float run = s3;
        #pragma unroll
        for (int d = 1; d < 32; d <<= 1) {
            float u = __shfl_up_sync(0xffffffffu, run, d);
            if (lane >= d) run += u;
        }
        const float off = run - s3;
        if (lane < 25) {
            float* sl = smt[r] + 84 * lane + C1 + c;
            sl[0]      = off + s0;
            sl[C1]     = off + s1;
            sl[2 * C1] = off + s2;
            sl[3 * C1] = off + s3;
        }
    }
    __syncthreads();

    // --- 4 bulk async row stores, single wait
    if (t == 0) {
        asm volatile("fence.proxy.async.shared::cta;" ::: "memory");
        float* gd = g_integral + ((size_t)jl * HP + ybase) * ROW_S;
        #pragma unroll
        for (int r = 0; r < RPB; r++) {
            unsigned sa;
            asm("{ .reg .u64 a; cvta.to.shared.u64 a, %1; cvt.u32.u64 %0, a; }"
                : "=r"(sa) : "l"(smt[r]));
            asm volatile(
                "cp.async.bulk.global.shared::cta.bulk_group [%0], [%1], %2;"
                :: "l"(gd + (size_t)r * ROW_S), "r"(sa), "r"(ROW_S * 4) : "memory");
        }
        asm volatile("cp.async.bulk.commit_group;" ::: "memory");
        asm volatile("cp.async.bulk.wait_group 0;" ::: "memory");
    }
}

// ---------------------------------------------------------------------------
// Kernel B: y-cumsum over float2 slots (1062/row); writes y=0 zero row then
// 100 dependent FADD2 steps, unroll 10 for load MLP.
// ---------------------------------------------------------------------------
__global__ void build_ysum() {
    const int jl    = blockIdx.y;
    const int slot2 = blockIdx.x * blockDim.x + threadIdx.x;
    if (slot2 >= ROW_S / 2) return;

    float2* p = (float2*)(g_integral + (size_t)jl * PLANE_S) + slot2;
    const int stride2 = ROW_S / 2;      // 1062

    float2 acc = make_float2(0.f, 0.f);
    p[0] = acc;                         // y = 0 row is zero
    #pragma unroll 10
    for (int y = 1; y <= H; y++) {
        float2 v = p[(size_t)y * stride2];
        acc.x += v.x; acc.y += v.y;
        p[(size_t)y * stride2] = acc;
    }
}

// ---------------------------------------------------------------------------
// Kernel C: one block per ROI. Phase 0: 196 threads precompute the 49x4
// corner base offsets (jl*PLANE_S + y*ROW_S + x*21) into smem — the main
// loop's addressing collapses to LDS + LDG[base + c]. Then register
// pre-reduction (16 jl-groups x 21 c), 21-thread final sum, warp softmax.
// ---------------------------------------------------------------------------
__global__ void __launch_bounds__(352) pool_softmax(const int* __restrict__ rois,
                                                    float* __restrict__ out) {
    const int roi = blockIdx.x;
    const int t   = threadIdx.x;
    __shared__ int   s_base[NJL * 4];  // [jl][corner]: a=y1x1, b=y0x1, d=y1x0, e=y0x0
    __shared__ float s_part[336];
    __shared__ float s_avg[C1];

    const int4 r = ((const int4*)rois)[roi];   // ymin, xmin, ymax, xmax
    const int ys = (r.z - r.x) / KK;
    const int xs = (r.w - r.y) / KK;

    if (t < NJL * 4) {
        const int jl = t >> 2, corner = t & 3;
        const int j = jl / KK, l = jl - j * KK;
        const int y = ((corner & 1) ? (r.x + j * ys) : (r.x + j * ys + ys));
        const int x = ((corner & 2) ? (r.y + l * xs) : (r.y + l * xs + xs));
        s_base[t] = jl * PLANE_S + y * ROW_S + x * C1;
    }
    __syncthreads();

    if (t < 336) {
        const int c   = t % C1;
        const int jl0 = t / C1;   // 0..15
        const float* P = g_integral + c;
        float part = 0.0f;
        #pragma unroll
        for (int jl = jl0; jl < NJL; jl += 16) {
            const int* bp = s_base + 4 * jl;
            const float a = P[bp[0]];
            const float b = P[bp[1]];
            const float d = P[bp[2]];
            const float e = P[bp[3]];
            part += (a - b) - (d - e);
        }
        s_part[t] = part;
    }
    __syncthreads();

    if (t < C1) {
        float acc = 0.0f;
        #pragma unroll
        for (int g = 0; g < 16; g++) acc += s_part[g * C1 + t];
        s_avg[t] = acc / (49.0f * (float)(ys * xs));
    }
    __syncthreads();

    if (t < 32) {
        const bool act = t < C1;
        float v = act ? s_avg[t] : -INFINITY;
        float m = v;
        #pragma unroll
        for (int o = 16; o; o >>= 1) m = fmaxf(m, __shfl_xor_sync(0xffffffffu, m, o));
        float e = act ? expf(v - m) : 0.0f;
        float sum = e;
        #pragma unroll
        for (int o = 16; o; o >>= 1) sum += __shfl_xor_sync(0xffffffffu, sum, o);
        if (act) out[(size_t)roi * C1 + t] = e / sum;
    }
}

// ---------------------------------------------------------------------------
extern "C" void kernel_launch(void* const* d_in, const int* in_sizes, int n_in,
                              void* d_out, int out_size) {
    const float* x    = (const float*)d_in[0];
    const int*   rois = (const int*)d_in[1];
    float*       out  = (float*)d_out;
    const int n_rois  = in_sizes[1] / 4;   // 2000

    dim3 gA(H / RPB, NJL);                  // 25 x 49
    build_xsum<<<gA, 672>>>(x);

    dim3 gB((ROW_S / 2 + 127) / 128, NJL);  // 9 x 49
    build_ysum<<<gB, 128>>>();

    pool_softmax<<<n_rois, 352>>>(rois, out);
}